// round 14
// baseline (speedup 1.0000x reference)
#include <cuda_runtime.h>
#include <cuda_fp16.h>
#include <math.h>

#define N_NODES 100000
#define N_EDGES 1600000
#define F_IN    128
#define HID     64
#define NCLS    40
#define H2STR   64          // padded h2 row stride (halves) -> 128B aligned rows
#define SCAN_B  512
#define N_SCANB ((N_NODES + SCAN_B - 1) / SCAN_B)   // 196
#define XSTR    72
#define WSTR    72
#define NHALF   50176       // 196 * 256: split point for the two pipelines

// ---------------- scratch (no allocations allowed) ----------------
__device__ int    g_is64;
__device__ int    g_cnt [N_NODES];
__device__ int    g_off [N_NODES + 1];
__device__ int    g_cur [N_NODES];
__device__ int    g_bsum [256];
__device__ int    g_csr_src[N_EDGES];
__device__ __align__(16) __half g_w1h[HID * F_IN];       // W1 transposed [n][k], fp16
__device__ __align__(16) __half g_h1 [N_NODES * HID];    // dinv*(x@W1), fp16
__device__ __align__(16) __half g_act[N_NODES * HID];    // relu(a1+b1), fp16
__device__ __align__(16) __half g_h2 [N_NODES * H2STR];  // dinv*(act@W2), fp16

__device__ __forceinline__ float dinv_of(int n) {
    return rsqrtf((float)(g_cnt[n] + 1));   // +1 self-loop
}

// ---------------- fp16 mma helper ----------------
__device__ __forceinline__ void mma_f16(float* d,
        unsigned a0, unsigned a1, unsigned a2, unsigned a3,
        unsigned b0, unsigned b1) {
    asm("mma.sync.aligned.m16n8k16.row.col.f32.f16.f16.f32 "
        "{%0,%1,%2,%3}, {%4,%5,%6,%7}, {%8,%9}, {%0,%1,%2,%3};"
        : "+f"(d[0]), "+f"(d[1]), "+f"(d[2]), "+f"(d[3])
        : "r"(a0), "r"(a1), "r"(a2), "r"(a3), "r"(b0), "r"(b1));
}

// ------- fused: edge dtype sniff + zero histogram + W1 fp16 transpose -------
__global__ void k_detect_zero(const int* __restrict__ ei32, const float* __restrict__ W1) {
    int i = blockIdx.x * blockDim.x + threadIdx.x;
    if (i < N_NODES) g_cnt[i] = 0;
    if (i < F_IN * HID) {                 // W1 row-major [k][n] -> g_w1h [n][k]
        int k = i >> 6, n = i & 63;
        g_w1h[n * F_IN + k] = __float2half(W1[i]);
    }
    if (i == 0) {
        int nz = 0;
        for (int j = 0; j < 256; j++) nz += (ei32[2 * j + 1] != 0);
        g_is64 = (nz == 0) ? 1 : 0;
    }
}

__device__ __forceinline__ int edge_at(const void* ei, long long idx) {
    int v;
    if (g_is64) v = (int)((const long long*)ei)[idx];
    else        v = ((const int*)ei)[idx];
    return min(max(v, 0), N_NODES - 1);   // wrong guess -> rel_err, not fault
}

// ---------------- CSR build ----------------
__global__ void k_hist(const void* __restrict__ ei) {
    int p = blockIdx.x * blockDim.x + threadIdx.x;
    int e = p * 2;
    if (e + 1 < N_EDGES) {
        int d0, d1;
        if (g_is64) {
            longlong2 dd = ((const longlong2*)((const long long*)ei + N_EDGES))[p];
            d0 = (int)dd.x; d1 = (int)dd.y;
        } else {
            int2 dd = ((const int2*)((const int*)ei + N_EDGES))[p];
            d0 = dd.x; d1 = dd.y;
        }
        d0 = min(max(d0, 0), N_NODES - 1);
        d1 = min(max(d1, 0), N_NODES - 1);
        atomicAdd(&g_cnt[d0], 1);
        atomicAdd(&g_cnt[d1], 1);
    } else if (e < N_EDGES) {
        atomicAdd(&g_cnt[edge_at(ei, (long long)N_EDGES + e)], 1);
    }
}

__global__ void k_scan_block() {
    __shared__ int sh[SCAN_B];
    int i = blockIdx.x * SCAN_B + threadIdx.x;
    int v = (i < N_NODES) ? g_cnt[i] : 0;
    sh[threadIdx.x] = v;
    __syncthreads();
#pragma unroll
    for (int off = 1; off < SCAN_B; off <<= 1) {
        int t = (threadIdx.x >= off) ? sh[threadIdx.x - off] : 0;
        __syncthreads();
        sh[threadIdx.x] += t;
        __syncthreads();
    }
    if (i < N_NODES) g_off[i] = sh[threadIdx.x] - v;
    if (threadIdx.x == SCAN_B - 1) g_bsum[blockIdx.x] = sh[SCAN_B - 1];
}

// finalize offsets (inline top-level scan) + reset scatter cursors
__global__ void k_scan_add() {
    __shared__ int pre[2];
    int blk0 = (blockIdx.x * 256) >> 9;
    if (threadIdx.x < 32) {
        int lane = threadIdx.x;
        int s0 = 0, s1 = 0;
        for (int j = lane; j < N_SCANB; j += 32) {
            int b = g_bsum[j];
            if (j < blk0)     s0 += b;
            if (j < blk0 + 1) s1 += b;
        }
#pragma unroll
        for (int off = 16; off > 0; off >>= 1) {
            s0 += __shfl_xor_sync(0xffffffffu, s0, off);
            s1 += __shfl_xor_sync(0xffffffffu, s1, off);
        }
        if (lane == 0) { pre[0] = s0; pre[1] = s1; }
    }
    __syncthreads();
    int i = blockIdx.x * 256 + threadIdx.x;
    if (i < N_NODES) {
        g_off[i] += pre[(i >> 9) - blk0];
        g_cur[i]  = 0;
    }
    if (i == 0) g_off[N_NODES] = N_EDGES;
}

// 2 edges per thread, vectorized loads
__global__ void k_scatter(const void* __restrict__ ei) {
    int p = blockIdx.x * blockDim.x + threadIdx.x;
    int e = p * 2;
    if (e + 1 < N_EDGES) {
        int s0, s1, d0, d1;
        if (g_is64) {
            longlong2 ss = ((const longlong2*)((const long long*)ei))[p];
            longlong2 dd = ((const longlong2*)((const long long*)ei + N_EDGES))[p];
            s0 = (int)ss.x; s1 = (int)ss.y; d0 = (int)dd.x; d1 = (int)dd.y;
        } else {
            int2 ss = ((const int2*)((const int*)ei))[p];
            int2 dd = ((const int2*)((const int*)ei + N_EDGES))[p];
            s0 = ss.x; s1 = ss.y; d0 = dd.x; d1 = dd.y;
        }
        s0 = min(max(s0, 0), N_NODES - 1);
        s1 = min(max(s1, 0), N_NODES - 1);
        d0 = min(max(d0, 0), N_NODES - 1);
        d1 = min(max(d1, 0), N_NODES - 1);
        g_csr_src[g_off[d0] + atomicAdd(&g_cur[d0], 1)] = s0;
        g_csr_src[g_off[d1] + atomicAdd(&g_cur[d1], 1)] = s1;
    } else if (e < N_EDGES) {
        int s = edge_at(ei, e);
        int d = edge_at(ei, (long long)N_EDGES + e);
        g_csr_src[g_off[d] + atomicAdd(&g_cur[d], 1)] = s;
    }
}

// -------- GEMM1 (fp16 mma): h1 = fp16(dinv * (x @ W1)) ----------------------
__global__ void __launch_bounds__(256, 4)
k_gemm1(const float* __restrict__ x) {
    __shared__ __align__(16) __half Xs[128 * XSTR];
    __shared__ __align__(16) __half Wn[64 * WSTR];
    const int t    = threadIdx.x;
    const int wid  = t >> 5, lane = t & 31;
    const int g    = lane >> 2, l = lane & 3;
    const int warpRow = (wid & 3) * 32;
    const int warpCol = (wid >> 2) * 32;
    const int row0 = blockIdx.x * 128;

    float acc[2][4][4];
#pragma unroll
    for (int mt = 0; mt < 2; mt++)
#pragma unroll
        for (int nt = 0; nt < 4; nt++)
#pragma unroll
            for (int c = 0; c < 4; c++) acc[mt][nt][c] = 0.0f;

    for (int kc = 0; kc < 2; kc++) {
#pragma unroll
        for (int j = 0; j < 8; j++) {
            int idx = t + j * 256;
            int r   = idx >> 4;
            int kq  = idx & 15;
            float4 v = make_float4(0.f, 0.f, 0.f, 0.f);
            if (row0 + r < N_NODES)
                v = *(const float4*)&x[(size_t)(row0 + r) * F_IN + kc * 64 + kq * 4];
            __half2 p0 = __floats2half2_rn(v.x, v.y);
            __half2 p1 = __floats2half2_rn(v.z, v.w);
            *(uint2*)&Xs[r * XSTR + kq * 4] =
                make_uint2(*(unsigned*)&p0, *(unsigned*)&p1);
        }
#pragma unroll
        for (int j = 0; j < 2; j++) {
            int idx = t + j * 256;
            int n   = idx >> 3;
            int q   = idx & 7;
            *(uint4*)&Wn[n * WSTR + q * 8] =
                *(const uint4*)&g_w1h[n * F_IN + kc * 64 + q * 8];
        }
        __syncthreads();

#pragma unroll
        for (int ks = 0; ks < 4; ks++) {
            int kk = ks * 16;
            unsigned b0[4], b1[4];
#pragma unroll
            for (int nt = 0; nt < 4; nt++) {
                int N = warpCol + nt * 8 + g;
                b0[nt] = *(const unsigned*)&Wn[N * WSTR + kk + 2 * l];
                b1[nt] = *(const unsigned*)&Wn[N * WSTR + kk + 2 * l + 8];
            }
#pragma unroll
            for (int mt = 0; mt < 2; mt++) {
                int R = warpRow + mt * 16;
                unsigned a0 = *(const unsigned*)&Xs[(R + g) * XSTR + kk + 2 * l];
                unsigned a1 = *(const unsigned*)&Xs[(R + 8 + g) * XSTR + kk + 2 * l];
                unsigned a2 = *(const unsigned*)&Xs[(R + g) * XSTR + kk + 2 * l + 8];
                unsigned a3 = *(const unsigned*)&Xs[(R + 8 + g) * XSTR + kk + 2 * l + 8];
#pragma unroll
                for (int nt = 0; nt < 4; nt++)
                    mma_f16(acc[mt][nt], a0, a1, a2, a3, b0[nt], b1[nt]);
            }
        }
        __syncthreads();
    }

#pragma unroll
    for (int mt = 0; mt < 2; mt++) {
        int ra = row0 + warpRow + mt * 16 + g;
        int rb = ra + 8;
        float dva = (ra < N_NODES) ? dinv_of(ra) : 0.0f;
        float dvb = (rb < N_NODES) ? dinv_of(rb) : 0.0f;
#pragma unroll
        for (int nt = 0; nt < 4; nt++) {
            int col = warpCol + nt * 8 + 2 * l;
            if (ra < N_NODES)
                *(__half2*)&g_h1[(size_t)ra * HID + col] =
                    __floats2half2_rn(acc[mt][nt][0] * dva, acc[mt][nt][1] * dva);
            if (rb < N_NODES)
                *(__half2*)&g_h1[(size_t)rb * HID + col] =
                    __floats2half2_rn(acc[mt][nt][2] * dvb, acc[mt][nt][3] * dvb);
        }
    }
}

// ---- agg layer1 over node range [base, base+cnt): gather + relu -> g_act ---
__global__ void k_agg1(const float* __restrict__ b1, int base, int cnt) {
    __shared__ float bs[HID];
    if (threadIdx.x < HID) bs[threadIdx.x] = b1[threadIdx.x];
    __syncthreads();

    unsigned gid = blockIdx.x * blockDim.x + threadIdx.x;
    int w    = gid >> 5;
    int lane = threadIdx.x & 31;
    if (w >= cnt) return;
    int n = base + w;

    int beg = g_off[n], end = g_off[n + 1];
    float dv = dinv_of(n);

    float2 v = __half22float2(*(const __half2*)&g_h1[(size_t)n * HID + lane * 2]);
    float ax = v.x, ay = v.y;

    int e = beg;
    for (; e + 7 < end; e += 8) {
        int s[8];
#pragma unroll
        for (int j = 0; j < 8; j++) s[j] = g_csr_src[e + j];
        __half2 hv[8];
#pragma unroll
        for (int j = 0; j < 8; j++)
            hv[j] = *(const __half2*)&g_h1[(size_t)s[j] * HID + lane * 2];
#pragma unroll
        for (int j = 0; j < 8; j++) {
            float2 f = __half22float2(hv[j]);
            ax += f.x; ay += f.y;
        }
    }
    for (; e + 3 < end; e += 4) {
        int s[4];
#pragma unroll
        for (int j = 0; j < 4; j++) s[j] = g_csr_src[e + j];
        __half2 hv[4];
#pragma unroll
        for (int j = 0; j < 4; j++)
            hv[j] = *(const __half2*)&g_h1[(size_t)s[j] * HID + lane * 2];
#pragma unroll
        for (int j = 0; j < 4; j++) {
            float2 f = __half22float2(hv[j]);
            ax += f.x; ay += f.y;
        }
    }
    for (; e < end; e++) {
        int s = g_csr_src[e];
        float2 f = __half22float2(*(const __half2*)&g_h1[(size_t)s * HID + lane * 2]);
        ax += f.x; ay += f.y;
    }

    float act0 = fmaxf(fmaf(dv, ax, bs[2 * lane]),     0.0f);
    float act1 = fmaxf(fmaf(dv, ay, bs[2 * lane + 1]), 0.0f);
    *(__half2*)&g_act[(size_t)n * HID + lane * 2] = __floats2half2_rn(act0, act1);
}

// ---- GEMM2 over node range: h2s = fp16(dinv * (act @ W2)) ------------------
__global__ void __launch_bounds__(256)
k_gemm2(const float* __restrict__ W2, int base, int cnt) {
    __shared__ float Ws[HID * NCLS];
    const int t = threadIdx.x;
#pragma unroll
    for (int j = 0; j < 10; j++) Ws[t + j * 256] = W2[t + j * 256];
    __syncthreads();

    const int rg = t >> 2;
    const int cg = t & 3;
    const int row0 = base + blockIdx.x * 256 + rg * 4;
    const int lim  = min(base + cnt, N_NODES);

    float acc[4][10];
#pragma unroll
    for (int r = 0; r < 4; r++)
#pragma unroll
        for (int c = 0; c < 10; c++) acc[r][c] = 0.0f;

    for (int k = 0; k < HID; k += 2) {
        float wv0[10], wv1[10];
#pragma unroll
        for (int c = 0; c < 10; c++) {
            wv0[c] = Ws[k * NCLS + cg * 10 + c];
            wv1[c] = Ws[(k + 1) * NCLS + cg * 10 + c];
        }
#pragma unroll
        for (int r = 0; r < 4; r++) {
            int row = row0 + r;
            if (row < lim) {
                float2 a = __half22float2(
                    *(const __half2*)&g_act[(size_t)row * HID + k]);
#pragma unroll
                for (int c = 0; c < 10; c++) {
                    acc[r][c] = fmaf(a.x, wv0[c], acc[r][c]);
                    acc[r][c] = fmaf(a.y, wv1[c], acc[r][c]);
                }
            }
        }
    }
#pragma unroll
    for (int r = 0; r < 4; r++) {
        int row = row0 + r;
        if (row < lim) {
            float dv = dinv_of(row);
#pragma unroll
            for (int c = 0; c < 5; c++) {
                __half2 p = __floats2half2_rn(dv * acc[r][2 * c],
                                              dv * acc[r][2 * c + 1]);
                *(__half2*)&g_h2[(size_t)row * H2STR + cg * 10 + 2 * c] = p;
            }
        }
    }
}

// ------- agg layer2: 3 lane-groups, 4 edges in flight each + log_softmax ----
__global__ void k_agg2_softmax(float* __restrict__ out, const float* __restrict__ b2) {
    unsigned gid = blockIdx.x * blockDim.x + threadIdx.x;
    int n    = gid >> 5;
    int lane = threadIdx.x & 31;
    if (n >= N_NODES) return;

    int beg = g_off[n], end = g_off[n + 1];
    float dv = dinv_of(n);

    int grp = (lane >= 20) ? 2 : ((lane >= 10) ? 1 : 0);
    int sub = lane - grp * 10;           // class quad 0..9
    bool act = lane < 30;

    float4 acc = make_float4(0.f, 0.f, 0.f, 0.f);
    if (lane < 10) {                     // self-loop, group 0 only
        uint2 u = *(const uint2*)&g_h2[(size_t)n * H2STR + lane * 4];
        float2 a = __half22float2(*(__half2*)&u.x);
        float2 b = __half22float2(*(__half2*)&u.y);
        acc = make_float4(a.x, a.y, b.x, b.y);
    }

    for (int e = beg; e < end; e += 12) {   // 12 edges/warp-iter, 4 per group
        int idx[4], sv[4];
#pragma unroll
        for (int k = 0; k < 4; k++) {
            idx[k] = e + 3 * k + grp;
            sv[k]  = (act && idx[k] < end) ? g_csr_src[idx[k]] : -1;
        }
        uint2 u[4];
#pragma unroll
        for (int k = 0; k < 4; k++)
            if (sv[k] >= 0)
                u[k] = *(const uint2*)&g_h2[(size_t)sv[k] * H2STR + sub * 4];
#pragma unroll
        for (int k = 0; k < 4; k++) {
            if (sv[k] >= 0) {
                float2 a = __half22float2(*(__half2*)&u[k].x);
                float2 b = __half22float2(*(__half2*)&u[k].y);
                acc.x += a.x; acc.y += a.y; acc.z += b.x; acc.w += b.y;
            }
        }
    }

    {   // cross-group reduction -> lanes 0-9
        float t1, t2;
        t1 = __shfl_down_sync(0xffffffffu, acc.x, 10);
        t2 = __shfl_down_sync(0xffffffffu, acc.x, 20);
        acc.x += t1 + t2;
        t1 = __shfl_down_sync(0xffffffffu, acc.y, 10);
        t2 = __shfl_down_sync(0xffffffffu, acc.y, 20);
        acc.y += t1 + t2;
        t1 = __shfl_down_sync(0xffffffffu, acc.z, 10);
        t2 = __shfl_down_sync(0xffffffffu, acc.z, 20);
        acc.z += t1 + t2;
        t1 = __shfl_down_sync(0xffffffffu, acc.w, 10);
        t2 = __shfl_down_sync(0xffffffffu, acc.w, 20);
        acc.w += t1 + t2;
    }

    const float NEG_INF = __int_as_float(0xff800000);
    float4 z = make_float4(NEG_INF, NEG_INF, NEG_INF, NEG_INF);
    if (lane < 10) {
        float4 bb = *(const float4*)&b2[lane * 4];
        z.x = fmaf(dv, acc.x, bb.x);
        z.y = fmaf(dv, acc.y, bb.y);
        z.z = fmaf(dv, acc.z, bb.z);
        z.w = fmaf(dv, acc.w, bb.w);
    }

    float m4 = fmaxf(fmaxf(z.x, z.y), fmaxf(z.z, z.w));
#pragma unroll
    for (int off = 16; off > 0; off >>= 1)
        m4 = fmaxf(m4, __shfl_xor_sync(0xffffffffu, m4, off));

    float s4 = 0.0f;
    if (lane < 10)
        s4 = __expf(z.x - m4) + __expf(z.y - m4) + __expf(z.z - m4) + __expf(z.w - m4);
#pragma unroll
    for (int off = 16; off > 0; off >>= 1)
        s4 += __shfl_xor_sync(0xffffffffu, s4, off);

    float lse = m4 + __logf(s4);
    if (lane < 10)
        *(float4*)&out[(size_t)n * NCLS + lane * 4] =
            make_float4(z.x - lse, z.y - lse, z.z - lse, z.w - lse);
}

// ---------------- launch ----------------
extern "C" void kernel_launch(void* const* d_in, const int* in_sizes, int n_in,
                              void* d_out, int out_size) {
    const float* x  = nullptr;  const void* ei = nullptr;
    const float* W1 = nullptr;  const float* b1 = nullptr;
    const float* W2 = nullptr;  const float* b2 = nullptr;
    for (int i = 0; i < n_in; i++) {
        switch (in_sizes[i]) {
            case N_NODES * F_IN:  x  = (const float*)d_in[i]; break;
            case 2 * N_EDGES:     ei = d_in[i];               break;
            case F_IN * HID:      W1 = (const float*)d_in[i]; break;
            case HID:             b1 = (const float*)d_in[i]; break;
            case HID * NCLS:      W2 = (const float*)d_in[i]; break;
            case NCLS:            b2 = (const float*)d_in[i]; break;
            default: break;
        }
    }
    float* out = (float*)d_out;

    static cudaStream_t sB = nullptr;
    static cudaEvent_t  evFork = nullptr, evJoin = nullptr, evG = nullptr, evB = nullptr;
    if (sB == nullptr) {
        cudaStreamCreateWithFlags(&sB, cudaStreamNonBlocking);
        cudaEventCreateWithFlags(&evFork, cudaEventDisableTiming);
        cudaEventCreateWithFlags(&evJoin, cudaEventDisableTiming);
        cudaEventCreateWithFlags(&evG,    cudaEventDisableTiming);
        cudaEventCreateWithFlags(&evB,    cudaEventDisableTiming);
    }

    const int NB_N  = (N_NODES + 255) / 256;
    const int NB_H  = (N_EDGES / 2 + 255) / 256;
    const int CNT_A = NHALF;                 // 50176
    const int CNT_B = N_NODES - NHALF;       // 49824
    const int NW_A  = (CNT_A * 32 + 255) / 256;
    const int NW_B  = (CNT_B * 32 + 255) / 256;
    const int NB_W  = (N_NODES * 32 + 255) / 256;

    // main stream: detect+W1 convert -> hist, then fork
    k_detect_zero <<<NB_N, 256>>>((const int*)ei, W1);            // 1
    k_hist        <<<NB_H, 256>>>(ei);                            // 2
    cudaEventRecord(evFork, 0);
    cudaStreamWaitEvent(sB, evFork, 0);

    // chain A (main stream): gemm1
    k_gemm1       <<<(N_NODES + 127) / 128, 256>>>(x);            // 3
    cudaEventRecord(evG, 0);

    // chain B (side stream): CSR build
    k_scan_block  <<<N_SCANB, SCAN_B, 0, sB>>>();                 // 4 <- profiled
    k_scan_add    <<<NB_N, 256, 0, sB>>>();
    k_scatter     <<<NB_H, 256, 0, sB>>>(ei);
    cudaEventRecord(evJoin, sB);

    // cross-join: each pipeline needs gemm1 + CSR
    cudaStreamWaitEvent(0, evJoin, 0);     // s0 has gemm1, needs CSR
    cudaStreamWaitEvent(sB, evG, 0);       // sB has CSR, needs gemm1

    // two pipelines: {agg1, gemm2} on disjoint node halves
    k_agg1        <<<NW_A, 256, 0, 0 >>>(b1, 0,     CNT_A);
    k_agg1        <<<NW_B, 256, 0, sB>>>(b1, NHALF, CNT_B);
    k_gemm2       <<<(CNT_A + 255) / 256, 256, 0, 0 >>>(W2, 0,     CNT_A);
    k_gemm2       <<<(CNT_B + 255) / 256, 256, 0, sB>>>(W2, NHALF, CNT_B);
    cudaEventRecord(evB, sB);
    cudaStreamWaitEvent(0, evB, 0);

    // final: agg2 + softmax over all nodes (gathers cross the split)
    k_agg2_softmax<<<NB_W, 256>>>(out, b2);
}

// round 15
// speedup vs baseline: 1.0024x; 1.0024x over previous
#include <cuda_runtime.h>
#include <cuda_fp16.h>
#include <math.h>

#define N_NODES 100000
#define N_EDGES 1600000
#define F_IN    128
#define HID     64
#define NCLS    40
#define H2STR   64          // padded h2 row stride (halves) -> 128B aligned rows
#define SCAN_B  512
#define N_SCANB ((N_NODES + SCAN_B - 1) / SCAN_B)   // 196
#define XSTR    72
#define WSTR    72

// ---------------- scratch (no allocations allowed) ----------------
__device__ int    g_is64;
__device__ int    g_cnt [N_NODES];
__device__ int    g_off [N_NODES + 1];
__device__ int    g_cur [N_NODES];
__device__ int    g_bsum [256];
__device__ __align__(16) int g_csr_src[N_EDGES];
__device__ __align__(16) __half g_w1h[HID * F_IN];       // W1 transposed [n][k], fp16
__device__ __align__(16) __half g_h1 [N_NODES * HID];    // dinv*(x@W1), fp16
__device__ __align__(16) __half g_act[N_NODES * HID];    // relu(a1+b1), fp16
__device__ __align__(16) __half g_h2 [N_NODES * H2STR];  // dinv*(act@W2), fp16

__device__ __forceinline__ float dinv_of(int n) {
    return rsqrtf((float)(g_cnt[n] + 1));   // +1 self-loop
}

// ---------------- fp16 mma helper ----------------
__device__ __forceinline__ void mma_f16(float* d,
        unsigned a0, unsigned a1, unsigned a2, unsigned a3,
        unsigned b0, unsigned b1) {
    asm("mma.sync.aligned.m16n8k16.row.col.f32.f16.f16.f32 "
        "{%0,%1,%2,%3}, {%4,%5,%6,%7}, {%8,%9}, {%0,%1,%2,%3};"
        : "+f"(d[0]), "+f"(d[1]), "+f"(d[2]), "+f"(d[3])
        : "r"(a0), "r"(a1), "r"(a2), "r"(a3), "r"(b0), "r"(b1));
}

// ------- fused: edge dtype sniff + zero histogram + W1 fp16 transpose -------
__global__ void k_detect_zero(const int* __restrict__ ei32, const float* __restrict__ W1) {
    int i = blockIdx.x * blockDim.x + threadIdx.x;
    if (i < N_NODES) g_cnt[i] = 0;
    if (i < F_IN * HID) {                 // W1 row-major [k][n] -> g_w1h [n][k]
        int k = i >> 6, n = i & 63;
        g_w1h[n * F_IN + k] = __float2half(W1[i]);
    }
    if (i == 0) {
        int nz = 0;
        for (int j = 0; j < 256; j++) nz += (ei32[2 * j + 1] != 0);
        g_is64 = (nz == 0) ? 1 : 0;
    }
}

__device__ __forceinline__ int edge_at(const void* ei, long long idx) {
    int v;
    if (g_is64) v = (int)((const long long*)ei)[idx];
    else        v = ((const int*)ei)[idx];
    return min(max(v, 0), N_NODES - 1);   // wrong guess -> rel_err, not fault
}

// ---------------- CSR build ----------------
__global__ void k_hist(const void* __restrict__ ei) {
    int p = blockIdx.x * blockDim.x + threadIdx.x;
    int e = p * 2;
    if (e + 1 < N_EDGES) {
        int d0, d1;
        if (g_is64) {
            longlong2 dd = ((const longlong2*)((const long long*)ei + N_EDGES))[p];
            d0 = (int)dd.x; d1 = (int)dd.y;
        } else {
            int2 dd = ((const int2*)((const int*)ei + N_EDGES))[p];
            d0 = dd.x; d1 = dd.y;
        }
        d0 = min(max(d0, 0), N_NODES - 1);
        d1 = min(max(d1, 0), N_NODES - 1);
        atomicAdd(&g_cnt[d0], 1);
        atomicAdd(&g_cnt[d1], 1);
    } else if (e < N_EDGES) {
        atomicAdd(&g_cnt[edge_at(ei, (long long)N_EDGES + e)], 1);
    }
}

__global__ void k_scan_block() {
    __shared__ int sh[SCAN_B];
    int i = blockIdx.x * SCAN_B + threadIdx.x;
    int v = (i < N_NODES) ? g_cnt[i] : 0;
    sh[threadIdx.x] = v;
    __syncthreads();
#pragma unroll
    for (int off = 1; off < SCAN_B; off <<= 1) {
        int t = (threadIdx.x >= off) ? sh[threadIdx.x - off] : 0;
        __syncthreads();
        sh[threadIdx.x] += t;
        __syncthreads();
    }
    if (i < N_NODES) g_off[i] = sh[threadIdx.x] - v;
    if (threadIdx.x == SCAN_B - 1) g_bsum[blockIdx.x] = sh[SCAN_B - 1];
}

// finalize offsets (inline top-level scan) + reset scatter cursors
__global__ void k_scan_add() {
    __shared__ int pre[2];
    int blk0 = (blockIdx.x * 256) >> 9;
    if (threadIdx.x < 32) {
        int lane = threadIdx.x;
        int s0 = 0, s1 = 0;
        for (int j = lane; j < N_SCANB; j += 32) {
            int b = g_bsum[j];
            if (j < blk0)     s0 += b;
            if (j < blk0 + 1) s1 += b;
        }
#pragma unroll
        for (int off = 16; off > 0; off >>= 1) {
            s0 += __shfl_xor_sync(0xffffffffu, s0, off);
            s1 += __shfl_xor_sync(0xffffffffu, s1, off);
        }
        if (lane == 0) { pre[0] = s0; pre[1] = s1; }
    }
    __syncthreads();
    int i = blockIdx.x * 256 + threadIdx.x;
    if (i < N_NODES) {
        g_off[i] += pre[(i >> 9) - blk0];
        g_cur[i]  = 0;
    }
    if (i == 0) g_off[N_NODES] = N_EDGES;
}

// 2 edges per thread, vectorized loads
__global__ void k_scatter(const void* __restrict__ ei) {
    int p = blockIdx.x * blockDim.x + threadIdx.x;
    int e = p * 2;
    if (e + 1 < N_EDGES) {
        int s0, s1, d0, d1;
        if (g_is64) {
            longlong2 ss = ((const longlong2*)((const long long*)ei))[p];
            longlong2 dd = ((const longlong2*)((const long long*)ei + N_EDGES))[p];
            s0 = (int)ss.x; s1 = (int)ss.y; d0 = (int)dd.x; d1 = (int)dd.y;
        } else {
            int2 ss = ((const int2*)((const int*)ei))[p];
            int2 dd = ((const int2*)((const int*)ei + N_EDGES))[p];
            s0 = ss.x; s1 = ss.y; d0 = dd.x; d1 = dd.y;
        }
        s0 = min(max(s0, 0), N_NODES - 1);
        s1 = min(max(s1, 0), N_NODES - 1);
        d0 = min(max(d0, 0), N_NODES - 1);
        d1 = min(max(d1, 0), N_NODES - 1);
        g_csr_src[g_off[d0] + atomicAdd(&g_cur[d0], 1)] = s0;
        g_csr_src[g_off[d1] + atomicAdd(&g_cur[d1], 1)] = s1;
    } else if (e < N_EDGES) {
        int s = edge_at(ei, e);
        int d = edge_at(ei, (long long)N_EDGES + e);
        g_csr_src[g_off[d] + atomicAdd(&g_cur[d], 1)] = s;
    }
}

// -------- GEMM1 (fp16 mma): h1 = fp16(dinv * (x @ W1)) ----------------------
__global__ void __launch_bounds__(256, 4)
k_gemm1(const float* __restrict__ x) {
    __shared__ __align__(16) __half Xs[128 * XSTR];
    __shared__ __align__(16) __half Wn[64 * WSTR];
    const int t    = threadIdx.x;
    const int wid  = t >> 5, lane = t & 31;
    const int g    = lane >> 2, l = lane & 3;
    const int warpRow = (wid & 3) * 32;
    const int warpCol = (wid >> 2) * 32;
    const int row0 = blockIdx.x * 128;

    float acc[2][4][4];
#pragma unroll
    for (int mt = 0; mt < 2; mt++)
#pragma unroll
        for (int nt = 0; nt < 4; nt++)
#pragma unroll
            for (int c = 0; c < 4; c++) acc[mt][nt][c] = 0.0f;

    for (int kc = 0; kc < 2; kc++) {
#pragma unroll
        for (int j = 0; j < 8; j++) {
            int idx = t + j * 256;
            int r   = idx >> 4;
            int kq  = idx & 15;
            float4 v = make_float4(0.f, 0.f, 0.f, 0.f);
            if (row0 + r < N_NODES)
                v = *(const float4*)&x[(size_t)(row0 + r) * F_IN + kc * 64 + kq * 4];
            __half2 p0 = __floats2half2_rn(v.x, v.y);
            __half2 p1 = __floats2half2_rn(v.z, v.w);
            *(uint2*)&Xs[r * XSTR + kq * 4] =
                make_uint2(*(unsigned*)&p0, *(unsigned*)&p1);
        }
#pragma unroll
        for (int j = 0; j < 2; j++) {
            int idx = t + j * 256;
            int n   = idx >> 3;
            int q   = idx & 7;
            *(uint4*)&Wn[n * WSTR + q * 8] =
                *(const uint4*)&g_w1h[n * F_IN + kc * 64 + q * 8];
        }
        __syncthreads();

#pragma unroll
        for (int ks = 0; ks < 4; ks++) {
            int kk = ks * 16;
            unsigned b0[4], b1[4];
#pragma unroll
            for (int nt = 0; nt < 4; nt++) {
                int N = warpCol + nt * 8 + g;
                b0[nt] = *(const unsigned*)&Wn[N * WSTR + kk + 2 * l];
                b1[nt] = *(const unsigned*)&Wn[N * WSTR + kk + 2 * l + 8];
            }
#pragma unroll
            for (int mt = 0; mt < 2; mt++) {
                int R = warpRow + mt * 16;
                unsigned a0 = *(const unsigned*)&Xs[(R + g) * XSTR + kk + 2 * l];
                unsigned a1 = *(const unsigned*)&Xs[(R + 8 + g) * XSTR + kk + 2 * l];
                unsigned a2 = *(const unsigned*)&Xs[(R + g) * XSTR + kk + 2 * l + 8];
                unsigned a3 = *(const unsigned*)&Xs[(R + 8 + g) * XSTR + kk + 2 * l + 8];
#pragma unroll
                for (int nt = 0; nt < 4; nt++)
                    mma_f16(acc[mt][nt], a0, a1, a2, a3, b0[nt], b1[nt]);
            }
        }
        __syncthreads();
    }

#pragma unroll
    for (int mt = 0; mt < 2; mt++) {
        int ra = row0 + warpRow + mt * 16 + g;
        int rb = ra + 8;
        float dva = (ra < N_NODES) ? dinv_of(ra) : 0.0f;
        float dvb = (rb < N_NODES) ? dinv_of(rb) : 0.0f;
#pragma unroll
        for (int nt = 0; nt < 4; nt++) {
            int col = warpCol + nt * 8 + 2 * l;
            if (ra < N_NODES)
                *(__half2*)&g_h1[(size_t)ra * HID + col] =
                    __floats2half2_rn(acc[mt][nt][0] * dva, acc[mt][nt][1] * dva);
            if (rb < N_NODES)
                *(__half2*)&g_h1[(size_t)rb * HID + col] =
                    __floats2half2_rn(acc[mt][nt][2] * dvb, acc[mt][nt][3] * dvb);
        }
    }
}

// ---- agg layer1: fp16 gather + half2 accumulate + relu -> g_act (fp16) -----
// warp per dst node; lane holds features 2*lane, 2*lane+1 (one half2).
__global__ void k_agg1(const float* __restrict__ b1) {
    __shared__ float bs[HID];
    if (threadIdx.x < HID) bs[threadIdx.x] = b1[threadIdx.x];
    __syncthreads();

    unsigned gid = blockIdx.x * blockDim.x + threadIdx.x;
    int n    = gid >> 5;
    int lane = threadIdx.x & 31;
    if (n >= N_NODES) return;

    int beg = g_off[n], end = g_off[n + 1];
    float dv = dinv_of(n);

    // self-loop kept in fp32
    float2 selfv = __half22float2(*(const __half2*)&g_h1[(size_t)n * HID + lane * 2]);

    __half2 acc[4];
    const __half2 HZERO = __floats2half2_rn(0.0f, 0.0f);
#pragma unroll
    for (int j = 0; j < 4; j++) acc[j] = HZERO;

    int e = beg;
    // head: align e to 4 for int4 index loads
    while (e < end && (e & 3)) {
        int s = g_csr_src[e];
        acc[0] = __hadd2(acc[0], *(const __half2*)&g_h1[(size_t)s * HID + lane * 2]);
        e++;
    }
    for (; e + 7 < end; e += 8) {            // 2 int4 index loads + 8 gathers + 8 hadd2
        int4 i0 = *(const int4*)&g_csr_src[e];
        int4 i1 = *(const int4*)&g_csr_src[e + 4];
        __half2 hv[8];
        hv[0] = *(const __half2*)&g_h1[(size_t)i0.x * HID + lane * 2];
        hv[1] = *(const __half2*)&g_h1[(size_t)i0.y * HID + lane * 2];
        hv[2] = *(const __half2*)&g_h1[(size_t)i0.z * HID + lane * 2];
        hv[3] = *(const __half2*)&g_h1[(size_t)i0.w * HID + lane * 2];
        hv[4] = *(const __half2*)&g_h1[(size_t)i1.x * HID + lane * 2];
        hv[5] = *(const __half2*)&g_h1[(size_t)i1.y * HID + lane * 2];
        hv[6] = *(const __half2*)&g_h1[(size_t)i1.z * HID + lane * 2];
        hv[7] = *(const __half2*)&g_h1[(size_t)i1.w * HID + lane * 2];
#pragma unroll
        for (int j = 0; j < 8; j++) acc[j & 3] = __hadd2(acc[j & 3], hv[j]);
    }
    if (e + 3 < end) {                        // one int4 batch
        int4 i0 = *(const int4*)&g_csr_src[e];
        __half2 hv[4];
        hv[0] = *(const __half2*)&g_h1[(size_t)i0.x * HID + lane * 2];
        hv[1] = *(const __half2*)&g_h1[(size_t)i0.y * HID + lane * 2];
        hv[2] = *(const __half2*)&g_h1[(size_t)i0.z * HID + lane * 2];
        hv[3] = *(const __half2*)&g_h1[(size_t)i0.w * HID + lane * 2];
#pragma unroll
        for (int j = 0; j < 4; j++) acc[j] = __hadd2(acc[j], hv[j]);
        e += 4;
    }
    for (; e < end; e++) {
        int s = g_csr_src[e];
        acc[0] = __hadd2(acc[0], *(const __half2*)&g_h1[(size_t)s * HID + lane * 2]);
    }

    // merge in fp32 (pairwise)
    float2 f0 = __half22float2(acc[0]);
    float2 f1 = __half22float2(acc[1]);
    float2 f2 = __half22float2(acc[2]);
    float2 f3 = __half22float2(acc[3]);
    float ax = (f0.x + f1.x) + (f2.x + f3.x) + selfv.x;
    float ay = (f0.y + f1.y) + (f2.y + f3.y) + selfv.y;

    float act0 = fmaxf(fmaf(dv, ax, bs[2 * lane]),     0.0f);
    float act1 = fmaxf(fmaf(dv, ay, bs[2 * lane + 1]), 0.0f);
    *(__half2*)&g_act[(size_t)n * HID + lane * 2] = __floats2half2_rn(act0, act1);
}

// ---- GEMM2: h2s = fp16(dinv * (act @ W2))  (100000x64 @ 64x40) -------------
__global__ void __launch_bounds__(256)
k_gemm2(const float* __restrict__ W2) {
    __shared__ float Ws[HID * NCLS];
    const int t = threadIdx.x;
#pragma unroll
    for (int j = 0; j < 10; j++) Ws[t + j * 256] = W2[t + j * 256];
    __syncthreads();

    const int rg = t >> 2;
    const int cg = t & 3;
    const int row0 = blockIdx.x * 256 + rg * 4;

    float acc[4][10];
#pragma unroll
    for (int r = 0; r < 4; r++)
#pragma unroll
        for (int c = 0; c < 10; c++) acc[r][c] = 0.0f;

    for (int k = 0; k < HID; k += 2) {
        float wv0[10], wv1[10];
#pragma unroll
        for (int c = 0; c < 10; c++) {
            wv0[c] = Ws[k * NCLS + cg * 10 + c];
            wv1[c] = Ws[(k + 1) * NCLS + cg * 10 + c];
        }
#pragma unroll
        for (int r = 0; r < 4; r++) {
            int row = row0 + r;
            if (row < N_NODES) {
                float2 a = __half22float2(
                    *(const __half2*)&g_act[(size_t)row * HID + k]);
#pragma unroll
                for (int c = 0; c < 10; c++) {
                    acc[r][c] = fmaf(a.x, wv0[c], acc[r][c]);
                    acc[r][c] = fmaf(a.y, wv1[c], acc[r][c]);
                }
            }
        }
    }
#pragma unroll
    for (int r = 0; r < 4; r++) {
        int row = row0 + r;
        if (row < N_NODES) {
            float dv = dinv_of(row);
#pragma unroll
            for (int c = 0; c < 5; c++) {
                __half2 p = __floats2half2_rn(dv * acc[r][2 * c],
                                              dv * acc[r][2 * c + 1]);
                *(__half2*)&g_h2[(size_t)row * H2STR + cg * 10 + 2 * c] = p;
            }
        }
    }
}

// ------- agg layer2: 3 lane-groups, half2 accumulate + log_softmax ----------
__global__ void k_agg2_softmax(float* __restrict__ out, const float* __restrict__ b2) {
    unsigned gid = blockIdx.x * blockDim.x + threadIdx.x;
    int n    = gid >> 5;
    int lane = threadIdx.x & 31;
    if (n >= N_NODES) return;

    int beg = g_off[n], end = g_off[n + 1];
    float dv = dinv_of(n);

    int grp = (lane >= 20) ? 2 : ((lane >= 10) ? 1 : 0);
    int sub = lane - grp * 10;           // class quad 0..9
    bool act = lane < 30;

    // self-loop kept in fp32 (lane<10, group 0)
    float4 selfv = make_float4(0.f, 0.f, 0.f, 0.f);
    if (lane < 10) {
        uint2 u = *(const uint2*)&g_h2[(size_t)n * H2STR + lane * 4];
        float2 a = __half22float2(*(__half2*)&u.x);
        float2 b = __half22float2(*(__half2*)&u.y);
        selfv = make_float4(a.x, a.y, b.x, b.y);
    }

    const __half2 HZERO = __floats2half2_rn(0.0f, 0.0f);
    __half2 aA[2] = {HZERO, HZERO};      // classes sub*4+0,1 (two accumulators)
    __half2 aB[2] = {HZERO, HZERO};      // classes sub*4+2,3

    for (int e = beg; e < end; e += 12) {   // 12 edges/warp-iter, 4 per group
        int sv[4];
#pragma unroll
        for (int k = 0; k < 4; k++) {
            int idx = e + 3 * k + grp;
            sv[k] = (act && idx < end) ? g_csr_src[idx] : -1;
        }
        uint2 u[4];
#pragma unroll
        for (int k = 0; k < 4; k++)
            u[k] = (sv[k] >= 0)
                ? *(const uint2*)&g_h2[(size_t)sv[k] * H2STR + sub * 4]
                : make_uint2(0u, 0u);       // +0.0h pair: identity for hadd2
#pragma unroll
        for (int k = 0; k < 4; k++) {
            aA[k & 1] = __hadd2(aA[k & 1], *(__half2*)&u[k].x);
            aB[k & 1] = __hadd2(aB[k & 1], *(__half2*)&u[k].y);
        }
    }

    float2 fA0 = __half22float2(aA[0]), fA1 = __half22float2(aA[1]);
    float2 fB0 = __half22float2(aB[0]), fB1 = __half22float2(aB[1]);
    float4 acc = make_float4(fA0.x + fA1.x + selfv.x,
                             fA0.y + fA1.y + selfv.y,
                             fB0.x + fB1.x + selfv.z,
                             fB0.y + fB1.y + selfv.w);

    {   // cross-group reduction -> lanes 0-9
        float t1, t2;
        t1 = __shfl_down_sync(0xffffffffu, acc.x, 10);
        t2 = __shfl_down_sync(0xffffffffu, acc.x, 20);
        acc.x += t1 + t2;
        t1 = __shfl_down_sync(0xffffffffu, acc.y, 10);
        t2 = __shfl_down_sync(0xffffffffu, acc.y, 20);
        acc.y += t1 + t2;
        t1 = __shfl_down_sync(0xffffffffu, acc.z, 10);
        t2 = __shfl_down_sync(0xffffffffu, acc.z, 20);
        acc.z += t1 + t2;
        t1 = __shfl_down_sync(0xffffffffu, acc.w, 10);
        t2 = __shfl_down_sync(0xffffffffu, acc.w, 20);
        acc.w += t1 + t2;
    }

    const float NEG_INF = __int_as_float(0xff800000);
    float4 z = make_float4(NEG_INF, NEG_INF, NEG_INF, NEG_INF);
    if (lane < 10) {
        float4 bb = *(const float4*)&b2[lane * 4];
        z.x = fmaf(dv, acc.x, bb.x);
        z.y = fmaf(dv, acc.y, bb.y);
        z.z = fmaf(dv, acc.z, bb.z);
        z.w = fmaf(dv, acc.w, bb.w);
    }

    float m4 = fmaxf(fmaxf(z.x, z.y), fmaxf(z.z, z.w));
#pragma unroll
    for (int off = 16; off > 0; off >>= 1)
        m4 = fmaxf(m4, __shfl_xor_sync(0xffffffffu, m4, off));

    float s4 = 0.0f;
    if (lane < 10)
        s4 = __expf(z.x - m4) + __expf(z.y - m4) + __expf(z.z - m4) + __expf(z.w - m4);
#pragma unroll
    for (int off = 16; off > 0; off >>= 1)
        s4 += __shfl_xor_sync(0xffffffffu, s4, off);

    float lse = m4 + __logf(s4);
    if (lane < 10)
        *(float4*)&out[(size_t)n * NCLS + lane * 4] =
            make_float4(z.x - lse, z.y - lse, z.z - lse, z.w - lse);
}

// ---------------- launch ----------------
extern "C" void kernel_launch(void* const* d_in, const int* in_sizes, int n_in,
                              void* d_out, int out_size) {
    const float* x  = nullptr;  const void* ei = nullptr;
    const float* W1 = nullptr;  const float* b1 = nullptr;
    const float* W2 = nullptr;  const float* b2 = nullptr;
    for (int i = 0; i < n_in; i++) {
        switch (in_sizes[i]) {
            case N_NODES * F_IN:  x  = (const float*)d_in[i]; break;
            case 2 * N_EDGES:     ei = d_in[i];               break;
            case F_IN * HID:      W1 = (const float*)d_in[i]; break;
            case HID:             b1 = (const float*)d_in[i]; break;
            case HID * NCLS:      W2 = (const float*)d_in[i]; break;
            case NCLS:            b2 = (const float*)d_in[i]; break;
            default: break;
        }
    }
    float* out = (float*)d_out;

    static cudaStream_t sB = nullptr;
    static cudaEvent_t  evFork = nullptr, evJoin = nullptr;
    if (sB == nullptr) {
        cudaStreamCreateWithFlags(&sB, cudaStreamNonBlocking);
        cudaEventCreateWithFlags(&evFork, cudaEventDisableTiming);
        cudaEventCreateWithFlags(&evJoin, cudaEventDisableTiming);
    }

    const int NB_N = (N_NODES + 255) / 256;
    const int NB_H = (N_EDGES / 2 + 255) / 256;
    const int NB_W = (N_NODES * 32 + 255) / 256;

    // main stream: detect+W1 convert -> hist, then fork
    k_detect_zero <<<NB_N, 256>>>((const int*)ei, W1);        // 1
    k_hist        <<<NB_H, 256>>>(ei);                        // 2
    cudaEventRecord(evFork, 0);
    cudaStreamWaitEvent(sB, evFork, 0);

    // chain A (main stream): gemm1 (dinv computed inline)
    k_gemm1       <<<(N_NODES + 127) / 128, 256>>>(x);        // 3

    // chain B (side stream): scan_block -> scan_add(+top) -> scatter
    k_scan_block  <<<N_SCANB, SCAN_B, 0, sB>>>();             // 4 <- profiled
    k_scan_add    <<<NB_N, 256, 0, sB>>>();
    k_scatter     <<<NB_H, 256, 0, sB>>>(ei);
    cudaEventRecord(evJoin, sB);
    cudaStreamWaitEvent(0, evJoin, 0);

    // join: agg1 -> gemm2 -> agg2+softmax
    k_agg1        <<<NB_W, 256>>>(b1);
    k_gemm2       <<<NB_N, 256>>>(W2);
    k_agg2_softmax<<<NB_W, 256>>>(out, b2);
}

// round 17
// speedup vs baseline: 1.0288x; 1.0264x over previous
#include <cuda_runtime.h>
#include <cuda_fp16.h>
#include <math.h>

#define N_NODES 100000
#define N_EDGES 1600000
#define F_IN    128
#define HID     64
#define NCLS    40
#define H2STR   64          // padded h2 row stride (halves) -> 128B aligned rows
#define SCAN_B  512
#define N_SCANB ((N_NODES + SCAN_B - 1) / SCAN_B)   // 196
#define XSTR    72
#define WSTR    72

// ---------------- scratch (no allocations allowed) ----------------
__device__ int    g_is64;
__device__ int    g_cnt [N_NODES];
__device__ int    g_off [N_NODES + 1];
__device__ int    g_cur [N_NODES];
__device__ int    g_bsum [256];
__device__ __align__(16) int g_csr_src[N_EDGES];
__device__ __align__(16) __half g_h1 [N_NODES * HID];    // x@W1 raw, then dinv-scaled
__device__ __align__(16) __half g_act[N_NODES * HID];    // relu(a1+b1), fp16
__device__ __align__(16) __half g_h2 [N_NODES * H2STR];  // dinv*(act@W2), fp16

__device__ __forceinline__ float dinv_of(int n) {
    return rsqrtf((float)(g_cnt[n] + 1));   // +1 self-loop
}

// ---------------- fp16 mma helper ----------------
__device__ __forceinline__ void mma_f16(float* d,
        unsigned a0, unsigned a1, unsigned a2, unsigned a3,
        unsigned b0, unsigned b1) {
    asm("mma.sync.aligned.m16n8k16.row.col.f32.f16.f16.f32 "
        "{%0,%1,%2,%3}, {%4,%5,%6,%7}, {%8,%9}, {%0,%1,%2,%3};"
        : "+f"(d[0]), "+f"(d[1]), "+f"(d[2]), "+f"(d[3])
        : "r"(a0), "r"(a1), "r"(a2), "r"(a3), "r"(b0), "r"(b1));
}

// -------- GEMM1 (fp16 mma, fully self-contained): h1_raw = x @ W1 -----------
// Launched FIRST, no dependencies. W1 fp32 [k][n] transposed+converted in-kernel.
__global__ void __launch_bounds__(256, 4)
k_gemm1(const float* __restrict__ x, const float* __restrict__ W1) {
    __shared__ __align__(16) __half Xs[128 * XSTR];
    __shared__ __align__(16) __half Wn[64 * WSTR];   // [n][k] fp16
    const int t    = threadIdx.x;
    const int wid  = t >> 5, lane = t & 31;
    const int g    = lane >> 2, l = lane & 3;
    const int warpRow = (wid & 3) * 32;
    const int warpCol = (wid >> 2) * 32;
    const int row0 = blockIdx.x * 128;

    float acc[2][4][4];
#pragma unroll
    for (int mt = 0; mt < 2; mt++)
#pragma unroll
        for (int nt = 0; nt < 4; nt++)
#pragma unroll
            for (int c = 0; c < 4; c++) acc[mt][nt][c] = 0.0f;

    for (int kc = 0; kc < 2; kc++) {
        // X tile: 128 rows x 64 k floats -> fp16 smem
#pragma unroll
        for (int j = 0; j < 8; j++) {
            int idx = t + j * 256;
            int r   = idx >> 4;
            int kq  = idx & 15;
            float4 v = make_float4(0.f, 0.f, 0.f, 0.f);
            if (row0 + r < N_NODES)
                v = *(const float4*)&x[(size_t)(row0 + r) * F_IN + kc * 64 + kq * 4];
            __half2 p0 = __floats2half2_rn(v.x, v.y);
            __half2 p1 = __floats2half2_rn(v.z, v.w);
            *(uint2*)&Xs[r * XSTR + kq * 4] =
                make_uint2(*(unsigned*)&p0, *(unsigned*)&p1);
        }
        // W chunk: transpose-convert W1 fp32 [k][n] -> Wn fp16 [n][k]
#pragma unroll
        for (int j = 0; j < 16; j++) {
            int idx = t + j * 256;          // 0..4095
            int k   = idx >> 6;             // 0..63
            int n   = idx & 63;
            Wn[n * WSTR + k] = __float2half(W1[(size_t)(kc * 64 + k) * HID + n]);
        }
        __syncthreads();

#pragma unroll
        for (int ks = 0; ks < 4; ks++) {
            int kk = ks * 16;
            unsigned b0[4], b1[4];
#pragma unroll
            for (int nt = 0; nt < 4; nt++) {
                int N = warpCol + nt * 8 + g;
                b0[nt] = *(const unsigned*)&Wn[N * WSTR + kk + 2 * l];
                b1[nt] = *(const unsigned*)&Wn[N * WSTR + kk + 2 * l + 8];
            }
#pragma unroll
            for (int mt = 0; mt < 2; mt++) {
                int R = warpRow + mt * 16;
                unsigned a0 = *(const unsigned*)&Xs[(R + g) * XSTR + kk + 2 * l];
                unsigned a1 = *(const unsigned*)&Xs[(R + 8 + g) * XSTR + kk + 2 * l];
                unsigned a2 = *(const unsigned*)&Xs[(R + g) * XSTR + kk + 2 * l + 8];
                unsigned a3 = *(const unsigned*)&Xs[(R + 8 + g) * XSTR + kk + 2 * l + 8];
#pragma unroll
                for (int nt = 0; nt < 4; nt++)
                    mma_f16(acc[mt][nt], a0, a1, a2, a3, b0[nt], b1[nt]);
            }
        }
        __syncthreads();
    }

    // epilogue: store RAW fp16 (dinv applied later by k_scale)
#pragma unroll
    for (int mt = 0; mt < 2; mt++) {
        int ra = row0 + warpRow + mt * 16 + g;
        int rb = ra + 8;
#pragma unroll
        for (int nt = 0; nt < 4; nt++) {
            int col = warpCol + nt * 8 + 2 * l;
            if (ra < N_NODES)
                *(__half2*)&g_h1[(size_t)ra * HID + col] =
                    __floats2half2_rn(acc[mt][nt][0], acc[mt][nt][1]);
            if (rb < N_NODES)
                *(__half2*)&g_h1[(size_t)rb * HID + col] =
                    __floats2half2_rn(acc[mt][nt][2], acc[mt][nt][3]);
        }
    }
}

// ---------------- CSR build chain (side stream) ----------------
__global__ void k_zero() {
    int i = blockIdx.x * blockDim.x + threadIdx.x;
    if (i < N_NODES) g_cnt[i] = 0;
}

// hist with per-block dtype sniff; block 0 publishes g_is64
__global__ void k_hist(const int* __restrict__ ei32, const void* __restrict__ ei) {
    __shared__ int s_is64;
    if (threadIdx.x == 0) {
        int nz = 0;
#pragma unroll
        for (int j = 0; j < 8; j++) nz += (ei32[2 * j + 1] != 0);
        s_is64 = (nz == 0) ? 1 : 0;
        if (blockIdx.x == 0) g_is64 = s_is64;
    }
    __syncthreads();
    int is64 = s_is64;

    int p = blockIdx.x * blockDim.x + threadIdx.x;
    int e = p * 2;
    if (e + 1 < N_EDGES) {
        int d0, d1;
        if (is64) {
            longlong2 dd = ((const longlong2*)((const long long*)ei + N_EDGES))[p];
            d0 = (int)dd.x; d1 = (int)dd.y;
        } else {
            int2 dd = ((const int2*)((const int*)ei + N_EDGES))[p];
            d0 = dd.x; d1 = dd.y;
        }
        d0 = min(max(d0, 0), N_NODES - 1);
        d1 = min(max(d1, 0), N_NODES - 1);
        atomicAdd(&g_cnt[d0], 1);
        atomicAdd(&g_cnt[d1], 1);
    } else if (e < N_EDGES) {
        int d;
        if (is64) d = (int)((const long long*)ei)[(long long)N_EDGES + e];
        else      d = ((const int*)ei)[(long long)N_EDGES + e];
        d = min(max(d, 0), N_NODES - 1);
        atomicAdd(&g_cnt[d], 1);
    }
}

__global__ void k_scan_block() {
    __shared__ int sh[SCAN_B];
    int i = blockIdx.x * SCAN_B + threadIdx.x;
    int v = (i < N_NODES) ? g_cnt[i] : 0;
    sh[threadIdx.x] = v;
    __syncthreads();
#pragma unroll
    for (int off = 1; off < SCAN_B; off <<= 1) {
        int t = (threadIdx.x >= off) ? sh[threadIdx.x - off] : 0;
        __syncthreads();
        sh[threadIdx.x] += t;
        __syncthreads();
    }
    if (i < N_NODES) g_off[i] = sh[threadIdx.x] - v;
    if (threadIdx.x == SCAN_B - 1) g_bsum[blockIdx.x] = sh[SCAN_B - 1];
}

// finalize offsets (inline top-level scan) + reset scatter cursors
__global__ void k_scan_add() {
    __shared__ int pre[2];
    int blk0 = (blockIdx.x * 256) >> 9;
    if (threadIdx.x < 32) {
        int lane = threadIdx.x;
        int s0 = 0, s1 = 0;
        for (int j = lane; j < N_SCANB; j += 32) {
            int b = g_bsum[j];
            if (j < blk0)     s0 += b;
            if (j < blk0 + 1) s1 += b;
        }
#pragma unroll
        for (int off = 16; off > 0; off >>= 1) {
            s0 += __shfl_xor_sync(0xffffffffu, s0, off);
            s1 += __shfl_xor_sync(0xffffffffu, s1, off);
        }
        if (lane == 0) { pre[0] = s0; pre[1] = s1; }
    }
    __syncthreads();
    int i = blockIdx.x * 256 + threadIdx.x;
    if (i < N_NODES) {
        g_off[i] += pre[(i >> 9) - blk0];
        g_cur[i]  = 0;
    }
    if (i == 0) g_off[N_NODES] = N_EDGES;
}

// 2 edges per thread, vectorized loads
__global__ void k_scatter(const void* __restrict__ ei) {
    int is64 = g_is64;
    int p = blockIdx.x * blockDim.x + threadIdx.x;
    int e = p * 2;
    if (e + 1 < N_EDGES) {
        int s0, s1, d0, d1;
        if (is64) {
            longlong2 ss = ((const longlong2*)((const long long*)ei))[p];
            longlong2 dd = ((const longlong2*)((const long long*)ei + N_EDGES))[p];
            s0 = (int)ss.x; s1 = (int)ss.y; d0 = (int)dd.x; d1 = (int)dd.y;
        } else {
            int2 ss = ((const int2*)((const int*)ei))[p];
            int2 dd = ((const int2*)((const int*)ei + N_EDGES))[p];
            s0 = ss.x; s1 = ss.y; d0 = dd.x; d1 = dd.y;
        }
        s0 = min(max(s0, 0), N_NODES - 1);
        s1 = min(max(s1, 0), N_NODES - 1);
        d0 = min(max(d0, 0), N_NODES - 1);
        d1 = min(max(d1, 0), N_NODES - 1);
        g_csr_src[g_off[d0] + atomicAdd(&g_cur[d0], 1)] = s0;
        g_csr_src[g_off[d1] + atomicAdd(&g_cur[d1], 1)] = s1;
    } else if (e < N_EDGES) {
        int s, d;
        if (is64) {
            s = (int)((const long long*)ei)[e];
            d = (int)((const long long*)ei)[(long long)N_EDGES + e];
        } else {
            s = ((const int*)ei)[e];
            d = ((const int*)ei)[(long long)N_EDGES + e];
        }
        s = min(max(s, 0), N_NODES - 1);
        d = min(max(d, 0), N_NODES - 1);
        g_csr_src[g_off[d] + atomicAdd(&g_cur[d], 1)] = s;
    }
}

// ---- scale: h1 *= dinv (after gemm1 + hist); 8 halves per thread -----------
__global__ void k_scale() {
    int i = blockIdx.x * blockDim.x + threadIdx.x;   // uint4 index
    if (i < N_NODES * HID / 8) {
        int node = i >> 3;
        float dv = dinv_of(node);
        uint4 u = *(const uint4*)&g_h1[(size_t)i * 8];
        unsigned* w = &u.x;
#pragma unroll
        for (int j = 0; j < 4; j++) {
            float2 f = __half22float2(*(__half2*)&w[j]);
            __half2 p = __floats2half2_rn(f.x * dv, f.y * dv);
            w[j] = *(unsigned*)&p;
        }
        *(uint4*)&g_h1[(size_t)i * 8] = u;
    }
}

// ---- agg layer1: fp16 CSR gather (unroll-8, fp32 acc) + relu -> g_act ------
__global__ void k_agg1(const float* __restrict__ b1) {
    __shared__ float bs[HID];
    if (threadIdx.x < HID) bs[threadIdx.x] = b1[threadIdx.x];
    __syncthreads();

    unsigned gid = blockIdx.x * blockDim.x + threadIdx.x;
    int n    = gid >> 5;
    int lane = threadIdx.x & 31;
    if (n >= N_NODES) return;

    int beg = g_off[n], end = g_off[n + 1];
    float dv = dinv_of(n);

    float2 v = __half22float2(*(const __half2*)&g_h1[(size_t)n * HID + lane * 2]);
    float ax = v.x, ay = v.y;

    int e = beg;
    for (; e + 7 < end; e += 8) {
        int s[8];
#pragma unroll
        for (int j = 0; j < 8; j++) s[j] = g_csr_src[e + j];
        __half2 hv[8];
#pragma unroll
        for (int j = 0; j < 8; j++)
            hv[j] = *(const __half2*)&g_h1[(size_t)s[j] * HID + lane * 2];
#pragma unroll
        for (int j = 0; j < 8; j++) {
            float2 f = __half22float2(hv[j]);
            ax += f.x; ay += f.y;
        }
    }
    for (; e + 3 < end; e += 4) {
        int s[4];
#pragma unroll
        for (int j = 0; j < 4; j++) s[j] = g_csr_src[e + j];
        __half2 hv[4];
#pragma unroll
        for (int j = 0; j < 4; j++)
            hv[j] = *(const __half2*)&g_h1[(size_t)s[j] * HID + lane * 2];
#pragma unroll
        for (int j = 0; j < 4; j++) {
            float2 f = __half22float2(hv[j]);
            ax += f.x; ay += f.y;
        }
    }
    for (; e < end; e++) {
        int s = g_csr_src[e];
        float2 f = __half22float2(*(const __half2*)&g_h1[(size_t)s * HID + lane * 2]);
        ax += f.x; ay += f.y;
    }

    float act0 = fmaxf(fmaf(dv, ax, bs[2 * lane]),     0.0f);
    float act1 = fmaxf(fmaf(dv, ay, bs[2 * lane + 1]), 0.0f);
    *(__half2*)&g_act[(size_t)n * HID + lane * 2] = __floats2half2_rn(act0, act1);
}

// ---- GEMM2: h2s = fp16(dinv * (act @ W2))  (100000x64 @ 64x40) -------------
__global__ void __launch_bounds__(256)
k_gemm2(const float* __restrict__ W2) {
    __shared__ float Ws[HID * NCLS];
    const int t = threadIdx.x;
#pragma unroll
    for (int j = 0; j < 10; j++) Ws[t + j * 256] = W2[t + j * 256];
    __syncthreads();

    const int rg = t >> 2;
    const int cg = t & 3;
    const int row0 = blockIdx.x * 256 + rg * 4;

    float acc[4][10];
#pragma unroll
    for (int r = 0; r < 4; r++)
#pragma unroll
        for (int c = 0; c < 10; c++) acc[r][c] = 0.0f;

    for (int k = 0; k < HID; k += 2) {
        float wv0[10], wv1[10];
#pragma unroll
        for (int c = 0; c < 10; c++) {
            wv0[c] = Ws[k * NCLS + cg * 10 + c];
            wv1[c] = Ws[(k + 1) * NCLS + cg * 10 + c];
        }
#pragma unroll
        for (int r = 0; r < 4; r++) {
            int row = row0 + r;
            if (row < N_NODES) {
                float2 a = __half22float2(
                    *(const __half2*)&g_act[(size_t)row * HID + k]);
#pragma unroll
                for (int c = 0; c < 10; c++) {
                    acc[r][c] = fmaf(a.x, wv0[c], acc[r][c]);
                    acc[r][c] = fmaf(a.y, wv1[c], acc[r][c]);
                }
            }
        }
    }
#pragma unroll
    for (int r = 0; r < 4; r++) {
        int row = row0 + r;
        if (row < N_NODES) {
            float dv = dinv_of(row);
#pragma unroll
            for (int c = 0; c < 5; c++) {
                __half2 p = __floats2half2_rn(dv * acc[r][2 * c],
                                              dv * acc[r][2 * c + 1]);
                *(__half2*)&g_h2[(size_t)row * H2STR + cg * 10 + 2 * c] = p;
            }
        }
    }
}

// ------- agg layer2: 3 lane-groups, 4 edges in flight, fp32 + log_softmax ---
__global__ void k_agg2_softmax(float* __restrict__ out, const float* __restrict__ b2) {
    unsigned gid = blockIdx.x * blockDim.x + threadIdx.x;
    int n    = gid >> 5;
    int lane = threadIdx.x & 31;
    if (n >= N_NODES) return;

    int beg = g_off[n], end = g_off[n + 1];
    float dv = dinv_of(n);

    int grp = (lane >= 20) ? 2 : ((lane >= 10) ? 1 : 0);
    int sub = lane - grp * 10;           // class quad 0..9
    bool act = lane < 30;

    float4 acc = make_float4(0.f, 0.f, 0.f, 0.f);
    if (lane < 10) {                     // self-loop, group 0 only
        uint2 u = *(const uint2*)&g_h2[(size_t)n * H2STR + lane * 4];
        float2 a = __half22float2(*(__half2*)&u.x);
        float2 b = __half22float2(*(__half2*)&u.y);
        acc = make_float4(a.x, a.y, b.x, b.y);
    }

    for (int e = beg; e < end; e += 12) {   // 12 edges/warp-iter, 4 per group
        int sv[4];
#pragma unroll
        for (int k = 0; k < 4; k++) {
            int idx = e + 3 * k + grp;
            sv[k] = (act && idx < end) ? g_csr_src[idx] : -1;
        }
        uint2 u[4];
#pragma unroll
        for (int k = 0; k < 4; k++)
            if (sv[k] >= 0)
                u[k] = *(const uint2*)&g_h2[(size_t)sv[k] * H2STR + sub * 4];
#pragma unroll
        for (int k = 0; k < 4; k++) {
            if (sv[k] >= 0) {
                float2 a = __half22float2(*(__half2*)&u[k].x);
                float2 b = __half22float2(*(__half2*)&u[k].y);
                acc.x += a.x; acc.y += a.y; acc.z += b.x; acc.w += b.y;
            }
        }
    }

    {   // cross-group reduction -> lanes 0-9
        float t1, t2;
        t1 = __shfl_down_sync(0xffffffffu, acc.x, 10);
        t2 = __shfl_down_sync(0xffffffffu, acc.x, 20);
        acc.x += t1 + t2;
        t1 = __shfl_down_sync(0xffffffffu, acc.y, 10);
        t2 = __shfl_down_sync(0xffffffffu, acc.y, 20);
        acc.y += t1 + t2;
        t1 = __shfl_down_sync(0xffffffffu, acc.z, 10);
        t2 = __shfl_down_sync(0xffffffffu, acc.z, 20);
        acc.z += t1 + t2;
        t1 = __shfl_down_sync(0xffffffffu, acc.w, 10);
        t2 = __shfl_down_sync(0xffffffffu, acc.w, 20);
        acc.w += t1 + t2;
    }

    const float NEG_INF = __int_as_float(0xff800000);
    float4 z = make_float4(NEG_INF, NEG_INF, NEG_INF, NEG_INF);
    if (lane < 10) {
        float4 bb = *(const float4*)&b2[lane * 4];
        z.x = fmaf(dv, acc.x, bb.x);
        z.y = fmaf(dv, acc.y, bb.y);
        z.z = fmaf(dv, acc.z, bb.z);
        z.w = fmaf(dv, acc.w, bb.w);
    }

    float m4 = fmaxf(fmaxf(z.x, z.y), fmaxf(z.z, z.w));
#pragma unroll
    for (int off = 16; off > 0; off >>= 1)
        m4 = fmaxf(m4, __shfl_xor_sync(0xffffffffu, m4, off));

    float s4 = 0.0f;
    if (lane < 10)
        s4 = __expf(z.x - m4) + __expf(z.y - m4) + __expf(z.z - m4) + __expf(z.w - m4);
#pragma unroll
    for (int off = 16; off > 0; off >>= 1)
        s4 += __shfl_xor_sync(0xffffffffu, s4, off);

    float lse = m4 + __logf(s4);
    if (lane < 10)
        *(float4*)&out[(size_t)n * NCLS + lane * 4] =
            make_float4(z.x - lse, z.y - lse, z.z - lse, z.w - lse);
}

// ---------------- launch ----------------
extern "C" void kernel_launch(void* const* d_in, const int* in_sizes, int n_in,
                              void* d_out, int out_size) {
    const float* x  = nullptr;  const void* ei = nullptr;
    const float* W1 = nullptr;  const float* b1 = nullptr;
    const float* W2 = nullptr;  const float* b2 = nullptr;
    for (int i = 0; i < n_in; i++) {
        switch (in_sizes[i]) {
            case N_NODES * F_IN:  x  = (const float*)d_in[i]; break;
            case 2 * N_EDGES:     ei = d_in[i];               break;
            case F_IN * HID:      W1 = (const float*)d_in[i]; break;
            case HID:             b1 = (const float*)d_in[i]; break;
            case HID * NCLS:      W2 = (const float*)d_in[i]; break;
            case NCLS:            b2 = (const float*)d_in[i]; break;
            default: break;
        }
    }
    float* out = (float*)d_out;

    static cudaStream_t sB = nullptr;
    static cudaEvent_t  evFork = nullptr, evH = nullptr, evB = nullptr;
    if (sB == nullptr) {
        cudaStreamCreateWithFlags(&sB, cudaStreamNonBlocking);
        cudaEventCreateWithFlags(&evFork, cudaEventDisableTiming);
        cudaEventCreateWithFlags(&evH,    cudaEventDisableTiming);
        cudaEventCreateWithFlags(&evB,    cudaEventDisableTiming);
    }

    const int NB_N = (N_NODES + 255) / 256;
    const int NB_H = (N_EDGES / 2 + 255) / 256;
    const int NB_W = (N_NODES * 32 + 255) / 256;
    const int NB_S = (N_NODES * HID / 8 + 255) / 256;

    // Fork sB from the capturing stream BEFORE any sB work (capture rule:
    // a side stream joins a capture only via an event from the origin stream).
    cudaEventRecord(evFork, 0);
    cudaStreamWaitEvent(sB, evFork, 0);

    // s0: gemm1 starts immediately (no dependencies)
    k_gemm1     <<<(N_NODES + 127) / 128, 256>>>(x, W1);          // 1

    // sB: CSR chain, concurrent with gemm1
    k_zero      <<<NB_N, 256, 0, sB>>>();                         // 2
    k_hist      <<<NB_H, 256, 0, sB>>>((const int*)ei, ei);       // 3
    cudaEventRecord(evH, sB);
    k_scan_block<<<N_SCANB, SCAN_B, 0, sB>>>();                   // 4 <- profiled
    k_scan_add  <<<NB_N, 256, 0, sB>>>();
    k_scatter   <<<NB_H, 256, 0, sB>>>(ei);
    cudaEventRecord(evB, sB);

    // s0: scale h1 by dinv (needs gemm1 [stream order] + hist [event])
    cudaStreamWaitEvent(0, evH, 0);
    k_scale     <<<NB_S, 256>>>();

    // s0: aggregation chain (needs CSR)
    cudaStreamWaitEvent(0, evB, 0);
    k_agg1        <<<NB_W, 256>>>(b1);
    k_gemm2       <<<NB_N, 256>>>(W2);
    k_agg2_softmax<<<NB_W, 256>>>(out, b2);
}